// round 2
// baseline (speedup 1.0000x reference)
#include <cuda_runtime.h>
#include <math.h>

#define NN    96
#define INDIM 64
#define HID   256
#define ZDIM  64
#define TRIN  4656
#define GRIDN 96
#define NT    128
#define ITERS 50

// ------------- persistent device scratch (no allocations allowed) -------------
__device__ unsigned long long g_bar;        // monotonic barrier counter
__device__ int   g_cnt[NN * NN];
__device__ float g_dis[NN];
__device__ float g_degA[NN];
__device__ float g_tmp1[NN * HID];
__device__ float g_tmp2[NN * HID];
__device__ float g_h[NN * HID];
__device__ float g_gvec[HID];
__device__ float g_d1[HID];
__device__ float g_kl;
__device__ float g_vecb[TRIN];
__device__ float g_B[NN * NN];
__device__ float g_Bd[NN];
__device__ float g_degB[NN];
__device__ float g_recpart[NN];
__device__ float g_M[2 * NN * NN];          // ping-pong max-message matrix
__device__ float g_part[2 * NN];            // ping-pong norm partials

// grid barrier: monotonic target => safe across sequential graph replays
__device__ __forceinline__ void gsync() {
    __threadfence();                         // release (emits CCTL.IVALL, gpu scope)
    __syncthreads();
    if (threadIdx.x == 0) {
        unsigned long long old = atomicAdd(&g_bar, 1ULL);
        unsigned long long tgt = old - (old % (unsigned long long)GRIDN) + (unsigned long long)GRIDN;
        while (*(volatile unsigned long long*)&g_bar < tgt) { }
        __threadfence();                     // acquire + L1D invalidate
    }
    __syncthreads();
}

__device__ __forceinline__ float blk_sum(float v, volatile float* s_w) {
    __syncthreads();                         // protect s_w from previous use
    #pragma unroll
    for (int o = 16; o; o >>= 1) v += __shfl_down_sync(0xFFFFFFFFu, v, o);
    if ((threadIdx.x & 31) == 0) s_w[threadIdx.x >> 5] = v;
    __syncthreads();
    return s_w[0] + s_w[1] + s_w[2] + s_w[3];
}

extern "C" __global__ void __launch_bounds__(NT, 1)
gvae_kernel(const float* __restrict__ X, const int* __restrict__ EI, int E,
            const float* __restrict__ A,
            const float* __restrict__ W1, const float* __restrict__ B1,
            const float* __restrict__ G1, const float* __restrict__ BB1,
            const float* __restrict__ W2, const float* __restrict__ B2,
            const float* __restrict__ G2, const float* __restrict__ BB2,
            const float* __restrict__ MUW, const float* __restrict__ MUB,
            const float* __restrict__ LVW, const float* __restrict__ LVB,
            const float* __restrict__ D1W, const float* __restrict__ D1B,
            const float* __restrict__ D2W, const float* __restrict__ D2B,
            const float* __restrict__ EPS, float* __restrict__ OUT, int osz)
{
    const int bid = blockIdx.x, tid = threadIdx.x;
    __shared__ float s_An[NN];
    __shared__ float s_row[HID];
    __shared__ float s_w[4];
    __shared__ float s_z[ZDIM];
    __shared__ float s_x[NN];
    __shared__ float s_Bd[NN];
    __shared__ int   s_nbr[NN];
    __shared__ int   s_wcnt[4];

    // ---- stage 0: zero edge-count row, init norm partials of y_0 (||y0||=1) ----
    if (tid < NN) g_cnt[bid * NN + tid] = 0;
    if (tid == 0) g_part[bid] = 1.0f / (float)NN;
    gsync();

    // ---- stage 1: scatter edges (int atomics = deterministic) + self loop ----
    for (int e = bid * NT + tid; e < E; e += GRIDN * NT) {
        int s = EI[e], d = EI[E + e];
        atomicAdd(&g_cnt[d * NN + s], 1);
    }
    if (tid == 0) atomicAdd(&g_cnt[bid * NN + bid], 1);
    gsync();

    // ---- stage 2: degree -> dis, and degA ----
    {
        float v  = (tid < NN) ? (float)__ldcg(&g_cnt[bid * NN + tid]) : 0.f;
        float dg = blk_sum(v, s_w);
        float va = (tid < NN) ? A[bid * NN + tid] : 0.f;
        float dA = blk_sum(va, s_w);
        if (tid == 0) { g_dis[bid] = rsqrtf(dg); g_degA[bid] = dA; }
    }
    gsync();

    // normalized adjacency row (used by both GCN layers)
    {
        float db = __ldcg(&g_dis[bid]);
        if (tid < NN) s_An[tid] = db * __ldcg(&g_dis[tid]) * (float)__ldcg(&g_cnt[bid * NN + tid]);
    }
    // ---- layer 1: tmp1 = x @ W1 ----
    if (tid < INDIM) s_row[tid] = X[bid * INDIM + tid];
    __syncthreads();
    for (int f = tid; f < HID; f += NT) {
        float a0 = 0.f, a1 = 0.f;
        #pragma unroll 8
        for (int k = 0; k < INDIM; k += 2) {
            a0 += s_row[k]     * W1[k * HID + f];
            a1 += s_row[k + 1] * W1[(k + 1) * HID + f];
        }
        g_tmp1[bid * HID + f] = a0 + a1;
    }
    gsync();
    for (int f = tid; f < HID; f += NT) {
        float a0 = 0.f, a1 = 0.f;
        #pragma unroll 4
        for (int s = 0; s < NN; s += 2) {
            a0 += s_An[s]     * __ldcg(&g_tmp1[s * HID + f]);
            a1 += s_An[s + 1] * __ldcg(&g_tmp1[(s + 1) * HID + f]);
        }
        g_tmp2[bid * HID + f] = B1[f] + a0 + a1;
    }
    gsync();
    for (int f = bid; f < HID; f += GRIDN) {
        float v   = (tid < NN) ? __ldcg(&g_tmp2[tid * HID + f]) : 0.f;
        float m   = blk_sum(v, s_w) * (1.0f / NN);
        float d   = (tid < NN) ? v - m : 0.f;
        float var = blk_sum(d * d, s_w) * (1.0f / NN);
        float sc  = G1[f] * rsqrtf(var + 1e-5f);
        if (tid < NN) g_h[tid * HID + f] = fmaxf(d * sc + BB1[f], 0.f);
    }
    gsync();

    // ---- layer 2 ----
    for (int k = tid; k < HID; k += NT) s_row[k] = __ldcg(&g_h[bid * HID + k]);
    __syncthreads();
    for (int f = tid; f < HID; f += NT) {
        float a0 = 0.f, a1 = 0.f;
        #pragma unroll 8
        for (int k = 0; k < HID; k += 2) {
            a0 += s_row[k]     * W2[k * HID + f];
            a1 += s_row[k + 1] * W2[(k + 1) * HID + f];
        }
        g_tmp1[bid * HID + f] = a0 + a1;
    }
    gsync();
    for (int f = tid; f < HID; f += NT) {
        float a0 = 0.f, a1 = 0.f;
        #pragma unroll 4
        for (int s = 0; s < NN; s += 2) {
            a0 += s_An[s]     * __ldcg(&g_tmp1[s * HID + f]);
            a1 += s_An[s + 1] * __ldcg(&g_tmp1[(s + 1) * HID + f]);
        }
        g_tmp2[bid * HID + f] = B2[f] + a0 + a1;
    }
    gsync();
    for (int f = bid; f < HID; f += GRIDN) {
        float v   = (tid < NN) ? __ldcg(&g_tmp2[tid * HID + f]) : 0.f;
        float m   = blk_sum(v, s_w) * (1.0f / NN);
        float d   = (tid < NN) ? v - m : 0.f;
        float var = blk_sum(d * d, s_w) * (1.0f / NN);
        float sc  = G2[f] * rsqrtf(var + 1e-5f);
        if (tid < NN) g_h[tid * HID + f] = fmaxf(d * sc + BB2[f], 0.f);
    }
    gsync();

    // ---- sum pooling ----
    for (int f = bid; f < HID; f += GRIDN) {
        float v = (tid < NN) ? __ldcg(&g_h[tid * HID + f]) : 0.f;
        float s = blk_sum(v, s_w);
        if (tid == 0) g_gvec[f] = s;
    }
    gsync();

    // ---- VAE head + dec1 (block 0) ----
    if (bid == 0) {
        for (int k = tid; k < HID; k += NT) s_row[k] = __ldcg(&g_gvec[k]);
        __syncthreads();
        float klt = 0.f;
        if (tid < ZDIM) {
            float mu = MUB[tid], lv = LVB[tid];
            #pragma unroll 8
            for (int k = 0; k < HID; k++) {
                float gv = s_row[k];
                mu += gv * MUW[k * ZDIM + tid];
                lv += gv * LVW[k * ZDIM + tid];
            }
            s_z[tid] = mu + EPS[tid] * expf(0.5f * lv);
            klt = 1.f + lv - mu * mu - expf(lv);
        }
        float ks = blk_sum(klt, s_w);
        if (tid == 0) g_kl = -0.5f * ks * (1.0f / ZDIM);
        __syncthreads();
        for (int f = tid; f < HID; f += NT) {
            float acc = D1B[f];
            #pragma unroll
            for (int k = 0; k < ZDIM; k++) acc += s_z[k] * D1W[k * HID + f];
            g_d1[f] = fmaxf(acc, 0.f);
        }
    }
    gsync();

    // ---- dec2: vec = relu(d1) @ dec2_w + b  (streams 4.8 MB) ----
    for (int k = tid; k < HID; k += NT) s_row[k] = __ldcg(&g_d1[k]);
    __syncthreads();
    for (int o = bid * NT + tid; o < TRIN; o += GRIDN * NT) {
        float a0 = 0.f, a1 = 0.f, a2 = 0.f, a3 = 0.f;
        #pragma unroll 4
        for (int k = 0; k < HID; k += 4) {
            a0 += s_row[k]     * D2W[k * TRIN + o];
            a1 += s_row[k + 1] * D2W[(k + 1) * TRIN + o];
            a2 += s_row[k + 2] * D2W[(k + 2) * TRIN + o];
            a3 += s_row[k + 3] * D2W[(k + 3) * TRIN + o];
        }
        g_vecb[o] = D2B[o] + ((a0 + a1) + (a2 + a3));
    }
    gsync();

    // ---- build B, Bd, degB, BCE partials ----
    {
        float Bv = 0.f, rc = 0.f;
        if (tid < NN) {
            int i_ = bid < tid ? bid : tid;
            int j_ = bid < tid ? tid : bid;
            int o  = i_ * NN - (i_ * (i_ - 1)) / 2 + (j_ - i_);
            float v = __ldcg(&g_vecb[o]);
            Bv = 1.f / (1.f + expf(-v));
            g_B[bid * NN + tid] = Bv;
            if (tid == bid) g_Bd[bid] = Bv;
            if (tid >= bid) {
                float truth = A[bid * NN + tid];
                rc = fmaxf(v, 0.f) - v * truth + log1pf(expf(-fabsf(v)));
            }
        }
        float dB = blk_sum(Bv, s_w);
        float rs = blk_sum(rc, s_w);
        if (tid == 0) { g_degB[bid] = dB; g_recpart[bid] = rs; }
    }
    gsync();

    // ---- MPM setup: Q row -> registers, D value, deterministic neighbor list ----
    if (tid < NN) s_Bd[tid] = __ldcg(&g_Bd[tid]);
    {
        bool pred = (tid < NN) && (tid != bid) && (A[bid * NN + tid] != 0.f);
        unsigned mm = __ballot_sync(0xFFFFFFFFu, pred);
        int w = tid >> 5, lane = tid & 31;
        if (lane == 0) s_wcnt[w] = __popc(mm);
        __syncthreads();
        int base = 0;
        #pragma unroll
        for (int ww = 0; ww < 4; ww++) if (ww < w) base += s_wcnt[ww];
        if (pred) s_nbr[base + __popc(mm & ((1u << lane) - 1u))] = tid;
    }
    __syncthreads();
    const int nnb = s_wcnt[0] + s_wcnt[1] + s_wcnt[2] + s_wcnt[3];

    float q[NN];
    float Da = 0.f;
    if (tid < NN) {
        float Bda = s_Bd[tid];
        float Adi = A[bid * NN + bid];
        Da = Adi * Bda / (fabsf(__ldcg(&g_degA[bid]) - __ldcg(&g_degB[tid])) + 1.f);
        #pragma unroll
        for (int b = 0; b < NN; b++) {
            float qv = __ldcg(&g_B[tid * NN + b]) * Bda * s_Bd[b];
            q[b] = (b == tid) ? 0.f : qv;
        }
        s_x[tid] = 1.0f / (float)NN;
    } else {
        #pragma unroll
        for (int b = 0; b < NN; b++) q[b] = 0.f;
    }
    __syncthreads();

    // ---- MPM loop: ONE grid barrier per iteration (ping-pong M & partials,
    //      normalization deferred one step via positive homogeneity) ----
    for (int k = 0; k < ITERS; k++) {
        float* Mb = g_M + (k & 1) * (NN * NN);
        if (tid < NN) {
            float m0 = 0.f, m1 = 0.f, m2 = 0.f, m3 = 0.f;
            #pragma unroll
            for (int b = 0; b < NN; b += 4) {
                m0 = fmaxf(m0, q[b]     * s_x[b]);
                m1 = fmaxf(m1, q[b + 1] * s_x[b + 1]);
                m2 = fmaxf(m2, q[b + 2] * s_x[b + 2]);
                m3 = fmaxf(m3, q[b + 3] * s_x[b + 3]);
            }
            Mb[bid * NN + tid] = fmaxf(fmaxf(m0, m1), fmaxf(m2, m3));
        }
        gsync();
        float pv   = (tid < NN) ? __ldcg(&g_part[(k & 1) * NN + tid]) : 0.f;
        float invn = rsqrtf(blk_sum(pv, s_w));
        float xn = 0.f;
        if (tid < NN) {
            float msg = 0.f;
            for (int j = 0; j < nnb; j++) msg += __ldcg(&Mb[s_nbr[j] * NN + tid]);
            xn = (s_x[tid] * Da + msg) * invn;
        }
        float ps = blk_sum(xn * xn, s_w);
        if (tid == 0) g_part[((k + 1) & 1) * NN + bid] = ps;
        if (tid < NN) s_x[tid] = xn;
        __syncthreads();
    }
    gsync();

    // ---- final normalize + outputs ----
    {
        float pv   = (tid < NN) ? __ldcg(&g_part[(ITERS & 1) * NN + tid]) : 0.f;
        float invn = rsqrtf(blk_sum(pv, s_w));
        int off = (osz > NN * NN) ? (osz - NN * NN) : 0;   // scalar(s) before X
        if (osz >= NN * NN && tid < NN)
            OUT[off + bid * NN + tid] = s_x[tid] * invn;
        if (bid == 0) {
            float rp = (tid < NN) ? __ldcg(&g_recpart[tid]) : 0.f;
            float rs = blk_sum(rp, s_w);
            if (tid == 0 && (osz < NN * NN || off > 0))
                OUT[0] = rs * (1.0f / (float)TRIN) + __ldcg(&g_kl);
        }
    }
}

extern "C" void kernel_launch(void* const* d_in, const int* in_sizes, int n_in,
                              void* d_out, int out_size) {
    const float* X   = (const float*)d_in[0];
    const int*   EI  = (const int*)  d_in[1];
    const float* A   = (const float*)d_in[3];
    const float* W1  = (const float*)d_in[4];
    const float* B1  = (const float*)d_in[5];
    const float* G1  = (const float*)d_in[6];
    const float* BB1 = (const float*)d_in[7];
    const float* W2  = (const float*)d_in[8];
    const float* B2  = (const float*)d_in[9];
    const float* G2  = (const float*)d_in[10];
    const float* BB2 = (const float*)d_in[11];
    const float* MUW = (const float*)d_in[12];
    const float* MUB = (const float*)d_in[13];
    const float* LVW = (const float*)d_in[14];
    const float* LVB = (const float*)d_in[15];
    const float* D1W = (const float*)d_in[16];
    const float* D1B = (const float*)d_in[17];
    const float* D2W = (const float*)d_in[18];
    const float* D2B = (const float*)d_in[19];
    const float* EPS = (const float*)d_in[20];
    int E = in_sizes[1] / 2;

    gvae_kernel<<<GRIDN, NT>>>(X, EI, E, A, W1, B1, G1, BB1, W2, B2, G2, BB2,
                               MUW, MUB, LVW, LVB, D1W, D1B, D2W, D2B, EPS,
                               (float*)d_out, out_size);
}